// round 15
// baseline (speedup 1.0000x reference)
#include <cuda_runtime.h>
#include <cstdint>

#define B_   8
#define LQ   5376
#define NQ   (B_*LQ)   // 43008

// Scratch buffers (no cudaMalloc allowed)
__device__ float g_value[(size_t)NQ * 128];   // (B,Lq,16,8)
__device__ float g_offs [(size_t)NQ * 384];   // (B,Lq,16,3,4,2)
__device__ float g_attn [(size_t)NQ * 192];   // (B,Lq,16,12) raw logits

// ---------------------------------------------------------------------------
// Kernel 1: fused projection GEMM  x[NQ,128] @ [W_val | W_off | W_attn] + bias
// Tile 128 queries x 64 cols, K chunked by 32, 8x4 per-thread micro-tile.
// cp.async double-buffered pipeline (16B LDGSTS). Scalar FFMA inner loop
// (at the fp32 issue roofline; packed fp32 ruled out R6/R11/R14).
// 128-query tiles never straddle level/batch boundaries.
// ---------------------------------------------------------------------------
__global__ __launch_bounds__(256) void proj_kernel(
    const float* __restrict__ fm0, const float* __restrict__ fm1, const float* __restrict__ fm2,
    const float* __restrict__ Wv, const float* __restrict__ bv,
    const float* __restrict__ Wo, const float* __restrict__ bo,
    const float* __restrict__ Wa, const float* __restrict__ ba)
{
    __shared__ float As[2][32][128];   // [buf][k][r]  32 KB
    __shared__ float Ws[2][32][64];    // [buf][k][c]  16 KB

    const int tid = threadIdx.x;
    const int qg0 = blockIdx.x * 128;
    const int n0  = blockIdx.y * 64;

    // ---- level/batch resolved once per block (tile is one contiguous run) ----
    const int b  = qg0 / LQ;
    const int q0 = qg0 - b * LQ;
    const float* fmp; int HW, pos0;
    if (q0 < 4096)      { fmp = fm0; HW = 4096; pos0 = q0; }
    else if (q0 < 5120) { fmp = fm1; HW = 1024; pos0 = q0 - 4096; }
    else                { fmp = fm2; HW = 256;  pos0 = q0 - 5120; }
    const float* abase = fmp + (size_t)b * 128 * HW + pos0;

    // ---- W mapping: this block's 64 columns lie in exactly one matrix ----
    const float* Wm; const float* bm; int wstride; int nloc0;
    if (n0 < 128)      { Wm = Wv; bm = bv; wstride = 128; nloc0 = n0; }
    else if (n0 < 512) { Wm = Wo; bm = bo; wstride = 384; nloc0 = n0 - 128; }
    else               { Wm = Wa; bm = ba; wstride = 192; nloc0 = n0 - 512; }

    // ---- micro-tile mapping ----
    const int tx = tid & 15, ty = tid >> 4;   // 16 x 16
    const int r0 = ty * 8, c0 = tx * 4;

    float acc[8][4];
    #pragma unroll
    for (int i = 0; i < 8; i++)
        #pragma unroll
        for (int j = 0; j < 4; j++) acc[i][j] = 0.f;

    // ---- async chunk loader: 4x 16B for A, 2x 16B for W per thread ----
    auto load_chunk = [&](int kk, int buf) {
        #pragma unroll
        for (int j = 0; j < 4; j++) {
            int idx = j * 256 + tid;            // 0..1023
            int k   = idx >> 5;                 // 0..31
            int r4  = (idx & 31) << 2;          // 0,4,..,124
            uint32_t dst = (uint32_t)__cvta_generic_to_shared(&As[buf][k][r4]);
            const float* src = abase + (size_t)(kk + k) * HW + r4;
            asm volatile("cp.async.ca.shared.global [%0], [%1], 16;" :: "r"(dst), "l"(src));
        }
        #pragma unroll
        for (int j = 0; j < 2; j++) {
            int idx = j * 256 + tid;            // 0..511
            int k   = idx >> 4;                 // 0..31
            int c4  = (idx & 15) << 2;          // 0,4,..,60
            uint32_t dst = (uint32_t)__cvta_generic_to_shared(&Ws[buf][k][c4]);
            const float* src = Wm + (size_t)(kk + k) * wstride + nloc0 + c4;
            asm volatile("cp.async.ca.shared.global [%0], [%1], 16;" :: "r"(dst), "l"(src));
        }
        asm volatile("cp.async.commit_group;" ::: "memory");
    };

    load_chunk(0, 0);

    #pragma unroll
    for (int c = 0; c < 4; c++) {
        if (c < 3) {
            load_chunk((c + 1) * 32, (c + 1) & 1);
            asm volatile("cp.async.wait_group 1;" ::: "memory");
        } else {
            asm volatile("cp.async.wait_group 0;" ::: "memory");
        }
        __syncthreads();

        const int buf = c & 1;
        #pragma unroll
        for (int k = 0; k < 32; k++) {
            float4 a0 = *(const float4*)&As[buf][k][r0];
            float4 a1 = *(const float4*)&As[buf][k][r0 + 4];
            float4 w  = *(const float4*)&Ws[buf][k][c0];
            acc[0][0] += a0.x * w.x; acc[0][1] += a0.x * w.y; acc[0][2] += a0.x * w.z; acc[0][3] += a0.x * w.w;
            acc[1][0] += a0.y * w.x; acc[1][1] += a0.y * w.y; acc[1][2] += a0.y * w.z; acc[1][3] += a0.y * w.w;
            acc[2][0] += a0.z * w.x; acc[2][1] += a0.z * w.y; acc[2][2] += a0.z * w.z; acc[2][3] += a0.z * w.w;
            acc[3][0] += a0.w * w.x; acc[3][1] += a0.w * w.y; acc[3][2] += a0.w * w.z; acc[3][3] += a0.w * w.w;
            acc[4][0] += a1.x * w.x; acc[4][1] += a1.x * w.y; acc[4][2] += a1.x * w.z; acc[4][3] += a1.x * w.w;
            acc[5][0] += a1.y * w.x; acc[5][1] += a1.y * w.y; acc[5][2] += a1.y * w.z; acc[5][3] += a1.y * w.w;
            acc[6][0] += a1.z * w.x; acc[6][1] += a1.z * w.y; acc[6][2] += a1.z * w.z; acc[6][3] += a1.z * w.w;
            acc[7][0] += a1.w * w.x; acc[7][1] += a1.w * w.y; acc[7][2] += a1.w * w.z; acc[7][3] += a1.w * w.w;
        }
        __syncthreads();
    }

    // Epilogue: add bias, scatter to the right scratch buffer (q-major)
    float bias[4];
    #pragma unroll
    for (int j = 0; j < 4; j++) bias[j] = bm[nloc0 + c0 + j];

    if (n0 < 128) {
        #pragma unroll
        for (int i = 0; i < 8; i++) {
            size_t qg_w = (size_t)(qg0 + r0 + i);
            float4 v = make_float4(acc[i][0] + bias[0], acc[i][1] + bias[1],
                                   acc[i][2] + bias[2], acc[i][3] + bias[3]);
            *(float4*)&g_value[qg_w * 128 + n0 + c0] = v;
        }
    } else if (n0 < 512) {
        #pragma unroll
        for (int i = 0; i < 8; i++) {
            size_t qg_w = (size_t)(qg0 + r0 + i);
            #pragma unroll
            for (int j = 0; j < 4; j++)
                g_offs[qg_w * 384 + (n0 - 128) + c0 + j] = acc[i][j] + bias[j];
        }
    } else {
        #pragma unroll
        for (int i = 0; i < 8; i++) {
            size_t qg_w = (size_t)(qg0 + r0 + i);
            #pragma unroll
            for (int j = 0; j < 4; j++)
                g_attn[qg_w * 192 + (n0 - 512) + c0 + j] = acc[i][j] + bias[j];
        }
    }
}

// ---------------------------------------------------------------------------
// Kernel 2 (FUSED): softmax + bilinear sampling + output projection.
// Block = 4 consecutive queries (never straddles a level boundary), 256 thr.
// Phase 1: sampling into smem s_samp[4][128] (16 heads x 4 chan-pairs / q).
// Phase 2: 4x128 @ 128x128 GEMM, W_out staged via smem in 16-row chunks;
//          output written through smem transpose as float4 (4 consecutive
//          pos per n-row) into the (B,128,H,W) per-level layout.
// ---------------------------------------------------------------------------
__global__ __launch_bounds__(256) void sample_out_kernel(
    const float* __restrict__ Wout, const float* __restrict__ bout,
    float* __restrict__ out)
{
    __shared__ float s_attn[4][192];
    __shared__ float s_offs[4][384];
    __shared__ float s_samp[4][128];
    __shared__ float s_W[16][128];     // W_out chunk   8 KB
    __shared__ float s_O[4][129];      // output transpose (+pad)

    const int t   = threadIdx.x;
    const int qi  = t >> 6;          // 0..3 query slot
    const int lt  = t & 63;
    const int h   = lt >> 2;         // 0..15
    const int chp = lt & 3;          // channel pair 0..3

    const int qg = blockIdx.x * 4 + qi;
    const int b = qg / LQ;
    const int q = qg - b * LQ;
    int posq, Wq;
    if (q < 4096)      { posq = q;        Wq = 64; }
    else if (q < 5120) { posq = q - 4096; Wq = 32; }
    else               { posq = q - 5120; Wq = 16; }
    const float invWq = 1.f / (float)Wq;
    const float refx = ((posq % Wq) + 0.5f) * invWq;
    const float refy = ((posq / Wq) + 0.5f) * invWq;

    {
        const size_t abase = (size_t)qg * 192;
        const size_t obase = (size_t)qg * 384;
        #pragma unroll
        for (int i = 0; i < 3; i++) s_attn[qi][lt + i * 64] = g_attn[abase + lt + i * 64];
        #pragma unroll
        for (int i = 0; i < 6; i++) s_offs[qi][lt + i * 64] = g_offs[obase + lt + i * 64];
    }
    __syncthreads();

    // Softmax over the 12 (level,point) logits of this head
    float av[12];
    float m = -1e30f;
    #pragma unroll
    for (int p = 0; p < 12; p++) { av[p] = s_attn[qi][h * 12 + p]; m = fmaxf(m, av[p]); }
    float s = 0.f;
    #pragma unroll
    for (int p = 0; p < 12; p++) { av[p] = __expf(av[p] - m); s += av[p]; }
    const float inv = 1.f / s;

    const int Ws_[3] = {64, 32, 16};
    const int st [3] = {0, 4096, 5120};

    float2 acc = make_float2(0.f, 0.f);
    #pragma unroll
    for (int l = 0; l < 3; l++) {
        const int   Wl = Ws_[l];
        const float fW = (float)Wl;
        const float* vbase = g_value + ((size_t)(b * LQ + st[l])) * 128 + h * 8 + chp * 2;
        #pragma unroll
        for (int p = 0; p < 4; p++) {
            float ox = s_offs[qi][h * 24 + (l * 4 + p) * 2 + 0];
            float oy = s_offs[qi][h * 24 + (l * 4 + p) * 2 + 1];
            float x = (refx + ox / fW) * fW - 0.5f;
            float y = (refy + oy / fW) * fW - 0.5f;
            float x0f = floorf(x), y0f = floorf(y);
            int   x0 = (int)x0f,  y0 = (int)y0f;
            float wx1 = x - x0f, wx0 = 1.f - wx1;
            float wy1 = y - y0f, wy0 = 1.f - wy1;
            float aw = av[l * 4 + p] * inv;
            #pragma unroll
            for (int dy = 0; dy < 2; dy++) {
                int yi = y0 + dy;
                if ((unsigned)yi >= (unsigned)Wl) continue;
                float wy = dy ? wy1 : wy0;
                #pragma unroll
                for (int dx = 0; dx < 2; dx++) {
                    int xi = x0 + dx;
                    if ((unsigned)xi >= (unsigned)Wl) continue;
                    float wx = dx ? wx1 : wx0;
                    float w = aw * wy * wx;
                    float2 v = *(const float2*)&vbase[(size_t)(yi * Wl + xi) * 128];
                    acc.x += w * v.x;
                    acc.y += w * v.y;
                }
            }
        }
    }
    *(float2*)&s_samp[qi][h * 8 + chp * 2] = acc;

    // ---- Phase 2: out projection for this block's 4 queries ----
    const int n0 = lt * 2;           // 2 output cols per thread
    float o0 = 0.f, o1 = 0.f;

    for (int kc = 0; kc < 128; kc += 16) {
        __syncthreads();             // s_samp ready (first iter) / s_W reuse safe
        // stage W_out[kc..kc+16][0..128] : 2048 floats = 512 float4, 2/thread
        #pragma unroll
        for (int j = 0; j < 2; j++) {
            int id = j * 256 + t;            // 0..511
            int k  = id >> 5;                // 0..15
            int n4 = (id & 31) << 2;         // 0..124
            *(float4*)&s_W[k][n4] = *(const float4*)&Wout[(size_t)(kc + k) * 128 + n4];
        }
        __syncthreads();
        #pragma unroll
        for (int k = 0; k < 16; k++) {
            float2 w = *(const float2*)&s_W[k][n0];
            float sv = s_samp[qi][kc + k];
            o0 += sv * w.x;
            o1 += sv * w.y;
        }
    }

    // bias + transpose to s_O, then coalesced float4 store (4 consecutive pos)
    __syncthreads();
    s_O[qi][n0]     = o0 + bout[n0];
    s_O[qi][n0 + 1] = o1 + bout[n0 + 1];
    __syncthreads();

    if (t < 128) {
        const int n = t;
        const int qg_0 = blockIdx.x * 4;          // first query of block
        const int b0 = qg_0 / LQ;
        const int q_0 = qg_0 - b0 * LQ;
        float4 v = make_float4(s_O[0][n], s_O[1][n], s_O[2][n], s_O[3][n]);
        size_t addr;
        if (q_0 < 4096)      addr = ((size_t)(b0 * 128 + n)) * 4096 + q_0;
        else if (q_0 < 5120) addr = 4194304u + ((size_t)(b0 * 128 + n)) * 1024 + (q_0 - 4096);
        else                 addr = 5242880u + ((size_t)(b0 * 128 + n)) * 256  + (q_0 - 5120);
        *(float4*)&out[addr] = v;
    }
}

extern "C" void kernel_launch(void* const* d_in, const int* in_sizes, int n_in,
                              void* d_out, int out_size)
{
    const float* fm0   = (const float*)d_in[0];
    const float* fm1   = (const float*)d_in[1];
    const float* fm2   = (const float*)d_in[2];
    const float* W_off = (const float*)d_in[3];
    const float* b_off = (const float*)d_in[4];
    const float* W_att = (const float*)d_in[5];
    const float* b_att = (const float*)d_in[6];
    const float* W_val = (const float*)d_in[7];
    const float* b_val = (const float*)d_in[8];
    const float* W_out = (const float*)d_in[9];
    const float* b_out = (const float*)d_in[10];
    float* out = (float*)d_out;

    dim3 g1(NQ / 128, 11);
    proj_kernel<<<g1, 256>>>(fm0, fm1, fm2, W_val, b_val, W_off, b_off, W_att, b_att);

    sample_out_kernel<<<NQ / 4, 256>>>(W_out, b_out, out);
}

// round 17
// speedup vs baseline: 1.0259x; 1.0259x over previous
#include <cuda_runtime.h>
#include <cuda_bf16.h>
#include <cstdint>

#define B_   8
#define LQ   5376
#define NQ   (B_*LQ)   // 43008

// Scratch buffers (no cudaMalloc allowed)
__device__ float g_value[(size_t)NQ * 128];   // (B,Lq,16,8)
__device__ float g_offs [(size_t)NQ * 384];   // (B,Lq,16,3,4,2)
__device__ float g_attn [(size_t)NQ * 192];   // (B,Lq,16,12) raw logits
__device__ float g_sampled[(size_t)NQ * 128]; // (B,Lq,16,8) after sampling
__device__ __nv_bfloat16 g_Whi[704 * 128];    // W^T split hi, [n][k]
__device__ __nv_bfloat16 g_Wlo[704 * 128];    // W^T split lo

// ---------------------------------------------------------------------------
// Kernel 0: W^T bf16 hi/lo split. n: 0..127 = W_val, 128..511 = W_off,
// 512..703 = W_attn.
// ---------------------------------------------------------------------------
__global__ void prep_kernel(const float* __restrict__ Wv,
                            const float* __restrict__ Wo,
                            const float* __restrict__ Wa)
{
    const int n = blockIdx.x;
    const int k = threadIdx.x;
    const float* src; int stride, nl;
    if (n < 128)      { src = Wv; stride = 128; nl = n; }
    else if (n < 512) { src = Wo; stride = 384; nl = n - 128; }
    else              { src = Wa; stride = 192; nl = n - 512; }
    float w = src[(size_t)k * stride + nl];
    __nv_bfloat16 hi = __float2bfloat16_rn(w);
    float resid = w - __bfloat162float(hi);
    g_Whi[(size_t)n * 128 + k] = hi;
    g_Wlo[(size_t)n * 128 + k] = __float2bfloat16_rn(resid);
}

// ---------------------------------------------------------------------------
// mma.sync helpers (sm_80-era PTX; compiles for plain sm_103)
// ---------------------------------------------------------------------------
__device__ __forceinline__ void mma_bf16(float c[4],
                                         const uint32_t a[4], const uint32_t b[2]) {
    asm volatile(
        "mma.sync.aligned.m16n8k16.row.col.f32.bf16.bf16.f32 "
        "{%0,%1,%2,%3}, {%4,%5,%6,%7}, {%8,%9}, {%0,%1,%2,%3};"
        : "+f"(c[0]), "+f"(c[1]), "+f"(c[2]), "+f"(c[3])
        : "r"(a[0]), "r"(a[1]), "r"(a[2]), "r"(a[3]), "r"(b[0]), "r"(b[1]));
}
__device__ __forceinline__ void ldm_x4_trans(uint32_t r[4], uint32_t addr) {
    asm volatile("ldmatrix.sync.aligned.m8n8.x4.trans.shared.b16 {%0,%1,%2,%3}, [%4];"
                 : "=r"(r[0]), "=r"(r[1]), "=r"(r[2]), "=r"(r[3]) : "r"(addr));
}
__device__ __forceinline__ void ldm_x4(uint32_t r[4], uint32_t addr) {
    asm volatile("ldmatrix.sync.aligned.m8n8.x4.shared.b16 {%0,%1,%2,%3}, [%4];"
                 : "=r"(r[0]), "=r"(r[1]), "=r"(r[2]), "=r"(r[3]) : "r"(addr));
}

// smem layout (bytes): As/Bs strides padded to 136 elems (272B) for
// conflict-free ldmatrix (bank stride 4)
#define A_STRIDE 136
#define B_STRIDE 136
#define OFF_AH   0
#define OFF_AL   (OFF_AH + 128 * A_STRIDE * 2)   // 34816
#define OFF_BH   (OFF_AL + 128 * A_STRIDE * 2)   // 69632
#define OFF_BL   (OFF_BH + 64 * B_STRIDE * 2)    // 87040
#define SMEM_TOTAL (OFF_BL + 64 * B_STRIDE * 2)  // 104448

// ---------------------------------------------------------------------------
// Kernel 1: projection GEMM on HMMA (mma.sync bf16, 3-term split).
// Block: 128q x 64n, K=128 single-shot. 8 warps = 4(M) x 2(N) of 32x32.
// A gathered fp32 -> split -> As[k][m] bf16 (ldmatrix .trans);
// B pre-split  -> Bs[n][k] bf16 (ldmatrix non-trans).
// 128-query tiles never straddle level/batch boundaries.
// ---------------------------------------------------------------------------
__global__ __launch_bounds__(256) void proj_mma(
    const float* __restrict__ fm0, const float* __restrict__ fm1, const float* __restrict__ fm2,
    const float* __restrict__ bv, const float* __restrict__ bo, const float* __restrict__ ba)
{
    extern __shared__ char smem[];
    const int tid = threadIdx.x;
    const int qg0 = blockIdx.x * 128;
    const int n0  = blockIdx.y * 64;

    // ---- level/batch resolved once per block ----
    const int b  = qg0 / LQ;
    const int q0 = qg0 - b * LQ;
    const float* fmp; int HW, pos0;
    if (q0 < 4096)      { fmp = fm0; HW = 4096; pos0 = q0; }
    else if (q0 < 5120) { fmp = fm1; HW = 1024; pos0 = q0 - 4096; }
    else                { fmp = fm2; HW = 256;  pos0 = q0 - 5120; }
    const float* abase = fmp + (size_t)b * 128 * HW + pos0;

    const float* bm; int nloc0;
    if (n0 < 128)      { bm = bv; nloc0 = n0; }
    else if (n0 < 512) { bm = bo; nloc0 = n0 - 128; }
    else               { bm = ba; nloc0 = n0 - 512; }

    // ---- stage A: gather fp32, split hi/lo, pack pairs, store [k][m] ----
    {
        const int kb = tid >> 6;          // 0..3
        const int qp = tid & 63;          // q-pair index (m = 2*qp)
        #pragma unroll
        for (int p = 0; p < 32; p++) {
            int k = p * 4 + kb;           // 0..127
            float2 v = *(const float2*)(abase + (size_t)k * HW + qp * 2);
            __nv_bfloat16 h0 = __float2bfloat16_rn(v.x);
            __nv_bfloat16 h1 = __float2bfloat16_rn(v.y);
            __nv_bfloat16 l0 = __float2bfloat16_rn(v.x - __bfloat162float(h0));
            __nv_bfloat16 l1 = __float2bfloat16_rn(v.y - __bfloat162float(h1));
            uint32_t hw = ((uint32_t)__bfloat16_as_ushort(h1) << 16) | __bfloat16_as_ushort(h0);
            uint32_t lw = ((uint32_t)__bfloat16_as_ushort(l1) << 16) | __bfloat16_as_ushort(l0);
            int eoff = (k * A_STRIDE + qp * 2) * 2;      // byte offset
            *(uint32_t*)(smem + OFF_AH + eoff) = hw;
            *(uint32_t*)(smem + OFF_AL + eoff) = lw;
        }
    }

    // ---- stage B: pre-split bf16 [n][k] -> Bs[n][k] ----
    {
        const int n  = tid >> 2;          // 0..63
        const int kq = (tid & 3) * 32;    // 0,32,64,96
        const int gn = n0 + n;
        #pragma unroll
        for (int j = 0; j < 4; j++) {
            int ke = kq + j * 8;          // element offset in k
            uint4 dh = *(const uint4*)(g_Whi + (size_t)gn * 128 + ke);
            uint4 dl = *(const uint4*)(g_Wlo + (size_t)gn * 128 + ke);
            int eoff = (n * B_STRIDE + ke) * 2;
            *(uint4*)(smem + OFF_BH + eoff) = dh;
            *(uint4*)(smem + OFF_BL + eoff) = dl;
        }
    }
    __syncthreads();

    // ---- mma mainloop ----
    const int w    = tid >> 5;
    const int lane = tid & 31;
    const int wm = (w & 3) * 32;          // warp M origin (queries)
    const int wn = (w >> 2) * 32;         // warp N origin (cols)
    const int grp = lane >> 3, r8 = lane & 7;

    float c[2][4][4];
    #pragma unroll
    for (int tm = 0; tm < 2; tm++)
        #pragma unroll
        for (int tn = 0; tn < 4; tn++)
            #pragma unroll
            for (int i = 0; i < 4; i++) c[tm][tn][i] = 0.f;

    const uint32_t smem_u32 = (uint32_t)__cvta_generic_to_shared(smem);

    #pragma unroll
    for (int ks = 0; ks < 8; ks++) {
        uint32_t ah[2][4], al[2][4], bh[4][2], bl[4][2];
        // A frags (ldmatrix x4 trans): source block rows=k, cols=m
        #pragma unroll
        for (int tm = 0; tm < 2; tm++) {
            int krow = ks * 16 + ((grp & 2) ? 8 : 0) + r8;
            int mcol = wm + tm * 16 + ((grp & 1) ? 8 : 0);
            uint32_t off = (uint32_t)(krow * A_STRIDE + mcol) * 2;
            ldm_x4_trans(ah[tm], smem_u32 + OFF_AH + off);
            ldm_x4_trans(al[tm], smem_u32 + OFF_AL + off);
        }
        // B frags (x4 covers two n8 tiles): rows=n, cols=k
        #pragma unroll
        for (int tp = 0; tp < 2; tp++) {
            int nrow = wn + tp * 16 + ((grp & 2) ? 8 : 0) + r8;
            int kcol = ks * 16 + ((grp & 1) ? 8 : 0);
            uint32_t off = (uint32_t)(nrow * B_STRIDE + kcol) * 2;
            uint32_t th[4], tl[4];
            ldm_x4(th, smem_u32 + OFF_BH + off);
            ldm_x4(tl, smem_u32 + OFF_BL + off);
            bh[2 * tp][0] = th[0]; bh[2 * tp][1] = th[1];
            bh[2 * tp + 1][0] = th[2]; bh[2 * tp + 1][1] = th[3];
            bl[2 * tp][0] = tl[0]; bl[2 * tp][1] = tl[1];
            bl[2 * tp + 1][0] = tl[2]; bl[2 * tp + 1][1] = tl[3];
        }
        #pragma unroll
        for (int tm = 0; tm < 2; tm++)
            #pragma unroll
            for (int tn = 0; tn < 4; tn++) {
                mma_bf16(c[tm][tn], ah[tm], bh[tn]);
                mma_bf16(c[tm][tn], ah[tm], bl[tn]);
                mma_bf16(c[tm][tn], al[tm], bh[tn]);
            }
    }

    // ---- epilogue: bias + scatter ----
    const int qrow = lane >> 2;           // 0..7
    const int col2 = (lane & 3) * 2;      // 0,2,4,6
    #pragma unroll
    for (int tm = 0; tm < 2; tm++) {
        #pragma unroll
        for (int tn = 0; tn < 4; tn++) {
            int cn   = wn + tn * 8 + col2;            // 0..63 local col
            int nloc = nloc0 + cn;
            float b0f = bm[nloc], b1f = bm[nloc + 1];
            size_t ra = (size_t)(qg0 + wm + tm * 16 + qrow);
            size_t rb = ra + 8;
            float2 v0 = make_float2(c[tm][tn][0] + b0f, c[tm][tn][1] + b1f);
            float2 v1 = make_float2(c[tm][tn][2] + b0f, c[tm][tn][3] + b1f);
            if (n0 < 128) {
                *(float2*)&g_value[ra * 128 + nloc] = v0;
                *(float2*)&g_value[rb * 128 + nloc] = v1;
            } else if (n0 < 512) {
                *(float2*)&g_offs[ra * 384 + nloc] = v0;
                *(float2*)&g_offs[rb * 384 + nloc] = v1;
            } else {
                *(float2*)&g_attn[ra * 192 + nloc] = v0;
                *(float2*)&g_attn[rb * 192 + nloc] = v1;
            }
        }
    }
}

// ---------------------------------------------------------------------------
// Kernel 2: per-query softmax + bilinear sampling (R13, unchanged).
// ---------------------------------------------------------------------------
__global__ __launch_bounds__(256) void sample_kernel()
{
    const int t   = threadIdx.x;
    const int qi  = t >> 6;
    const int lt  = t & 63;
    const int h   = lt >> 2;
    const int chp = lt & 3;

    const int qg = blockIdx.x * 4 + qi;
    const int b = qg / LQ;
    const int q = qg - b * LQ;
    int posq, Wq;
    if (q < 4096)      { posq = q;        Wq = 64; }
    else if (q < 5120) { posq = q - 4096; Wq = 32; }
    else               { posq = q - 5120; Wq = 16; }
    const float invWq = 1.f / (float)Wq;
    const float refx = ((posq % Wq) + 0.5f) * invWq;
    const float refy = ((posq / Wq) + 0.5f) * invWq;

    __shared__ float s_attn[4][192];
    __shared__ float s_offs[4][384];
    {
        const size_t abase = (size_t)qg * 192;
        const size_t obase = (size_t)qg * 384;
        #pragma unroll
        for (int i = 0; i < 3; i++) s_attn[qi][lt + i * 64] = g_attn[abase + lt + i * 64];
        #pragma unroll
        for (int i = 0; i < 6; i++) s_offs[qi][lt + i * 64] = g_offs[obase + lt + i * 64];
    }
    __syncthreads();

    float av[12];
    float m = -1e30f;
    #pragma unroll
    for (int p = 0; p < 12; p++) { av[p] = s_attn[qi][h * 12 + p]; m = fmaxf(m, av[p]); }
    float s = 0.f;
    #pragma unroll
    for (int p = 0; p < 12; p++) { av[p] = __expf(av[p] - m); s += av[p]; }
    const float inv = 1.f / s;

    const int Ws_[3] = {64, 32, 16};
    const int st [3] = {0, 4096, 5120};

    float2 acc = make_float2(0.f, 0.f);
    #pragma unroll
    for (int l = 0; l < 3; l++) {
        const int   Wl = Ws_[l];
        const float fW = (float)Wl;
        const float* vbase = g_value + ((size_t)(b * LQ + st[l])) * 128 + h * 8 + chp * 2;
        #pragma unroll
        for (int p = 0; p < 4; p++) {
            float ox = s_offs[qi][h * 24 + (l * 4 + p) * 2 + 0];
            float oy = s_offs[qi][h * 24 + (l * 4 + p) * 2 + 1];
            float x = (refx + ox / fW) * fW - 0.5f;
            float y = (refy + oy / fW) * fW - 0.5f;
            float x0f = floorf(x), y0f = floorf(y);
            int   x0 = (int)x0f,  y0 = (int)y0f;
            float wx1 = x - x0f, wx0 = 1.f - wx1;
            float wy1 = y - y0f, wy0 = 1.f - wy1;
            float aw = av[l * 4 + p] * inv;
            #pragma unroll
            for (int dy = 0; dy < 2; dy++) {
                int yi = y0 + dy;
                if ((unsigned)yi >= (unsigned)Wl) continue;
                float wy = dy ? wy1 : wy0;
                #pragma unroll
                for (int dx = 0; dx < 2; dx++) {
                    int xi = x0 + dx;
                    if ((unsigned)xi >= (unsigned)Wl) continue;
                    float wx = dx ? wx1 : wx0;
                    float w = aw * wy * wx;
                    float2 v = *(const float2*)&vbase[(size_t)(yi * Wl + xi) * 128];
                    acc.x += w * v.x;
                    acc.y += w * v.y;
                }
            }
        }
    }
    *(float2*)&g_sampled[(size_t)qg * 128 + h * 8 + chp * 2] = acc;
}

// ---------------------------------------------------------------------------
// Kernel 3: output projection (R13, unchanged).
// ---------------------------------------------------------------------------
__global__ __launch_bounds__(256) void out_kernel(
    const float* __restrict__ Wout, const float* __restrict__ bout,
    float* __restrict__ out)
{
    __shared__ float As[64][65];
    __shared__ float Ws[64][64];
    __shared__ float Os[64][65];

    const int tid = threadIdx.x;
    const int qg0 = blockIdx.x * 64;
    const int n0  = blockIdx.y * 64;
    const int tx = tid & 15, ty = tid >> 4;
    const int r0 = ty * 4, c0 = tx * 4;

    float acc[4][4];
    #pragma unroll
    for (int i = 0; i < 4; i++)
        #pragma unroll
        for (int j = 0; j < 4; j++) acc[i][j] = 0.f;

    const int kl = tid & 63;
    const int rb = tid >> 6;

    for (int kk = 0; kk < 128; kk += 64) {
        #pragma unroll
        for (int i = 0; i < 16; i++) {
            int r_ = rb + 4 * i;
            As[r_][kl] = g_sampled[(size_t)(qg0 + r_) * 128 + kk + kl];
        }
        #pragma unroll
        for (int i = 0; i < 16; i++) {
            int k_ = rb + 4 * i;
            Ws[k_][kl] = Wout[(size_t)(kk + k_) * 128 + n0 + kl];
        }
        __syncthreads();
        #pragma unroll
        for (int k = 0; k < 64; k++) {
            float4 w = *(const float4*)&Ws[k][c0];
            float a0 = As[r0 + 0][k], a1 = As[r0 + 1][k];
            float a2 = As[r0 + 2][k], a3 = As[r0 + 3][k];
            acc[0][0] += a0 * w.x; acc[0][1] += a0 * w.y; acc[0][2] += a0 * w.z; acc[0][3] += a0 * w.w;
            acc[1][0] += a1 * w.x; acc[1][1] += a1 * w.y; acc[1][2] += a1 * w.z; acc[1][3] += a1 * w.w;
            acc[2][0] += a2 * w.x; acc[2][1] += a2 * w.y; acc[2][2] += a2 * w.z; acc[2][3] += a2 * w.w;
            acc[3][0] += a3 * w.x; acc[3][1] += a3 * w.y; acc[3][2] += a3 * w.z; acc[3][3] += a3 * w.w;
        }
        __syncthreads();
    }

    #pragma unroll
    for (int i = 0; i < 4; i++)
        #pragma unroll
        for (int j = 0; j < 4; j++)
            Os[r0 + i][c0 + j] = acc[i][j] + bout[n0 + c0 + j];
    __syncthreads();

    for (int cc = 0; cc < 64; cc += 4) {
        int c = cc + (tid >> 6);
        int r = tid & 63;
        int qg = qg0 + r;
        int b = qg / LQ;
        int q = qg - b * LQ;
        int n = n0 + c;
        size_t addr;
        if (q < 4096)      addr = ((size_t)(b * 128 + n)) * 4096 + q;
        else if (q < 5120) addr = 4194304u + ((size_t)(b * 128 + n)) * 1024 + (q - 4096);
        else               addr = 5242880u + ((size_t)(b * 128 + n)) * 256  + (q - 5120);
        out[addr] = Os[r][c];
    }
}

extern "C" void kernel_launch(void* const* d_in, const int* in_sizes, int n_in,
                              void* d_out, int out_size)
{
    const float* fm0   = (const float*)d_in[0];
    const float* fm1   = (const float*)d_in[1];
    const float* fm2   = (const float*)d_in[2];
    const float* W_off = (const float*)d_in[3];
    const float* b_off = (const float*)d_in[4];
    const float* W_att = (const float*)d_in[5];
    const float* b_att = (const float*)d_in[6];
    const float* W_val = (const float*)d_in[7];
    const float* b_val = (const float*)d_in[8];
    const float* W_out = (const float*)d_in[9];
    const float* b_out = (const float*)d_in[10];
    float* out = (float*)d_out;

    cudaFuncSetAttribute(proj_mma, cudaFuncAttributeMaxDynamicSharedMemorySize, SMEM_TOTAL);

    prep_kernel<<<704, 128>>>(W_val, W_off, W_att);

    dim3 g1(NQ / 128, 11);
    proj_mma<<<g1, 256, SMEM_TOTAL>>>(fm0, fm1, fm2, b_val, b_off, b_att);

    sample_kernel<<<NQ / 4, 256>>>();

    dim3 g3(NQ / 64, 2);
    out_kernel<<<g3, 256>>>(W_out, b_out, out);
}